// round 2
// baseline (speedup 1.0000x reference)
#include <cuda_runtime.h>
#include <math.h>

// Problem constants
constexpr int B_ = 8, N_ = 2048, F_ = 128, H_ = 128, O_ = 64;
constexpr int ROWS = B_ * N_;            // 16384
constexpr float NEG_INF = -1.0e9f;

// Output layout (tuple flattened in order):
// x_proj, logits, adj_A1, eye, z, z_positive, adj_A, Wa
constexpr long long OFF_XPROJ  = 0;
constexpr long long OFF_LOGITS = OFF_XPROJ  + (long long)B_ * N_ * O_;   //  1048576
constexpr long long OFF_ADJ1   = OFF_LOGITS + (long long)B_ * N_ * O_;   //  2097152
constexpr long long OFF_EYE    = OFF_ADJ1   + (long long)N_ * N_;        //  6291456
constexpr long long OFF_Z      = OFF_EYE    + (long long)N_ * N_;        // 10485760
constexpr long long OFF_ZPOS   = OFF_Z      + 1;                         // 10485761 (ODD -> 4B aligned only)
constexpr long long OFF_ADJA   = OFF_ZPOS   + (long long)N_ * N_;        // 14680065 (ODD -> 4B aligned only)
constexpr long long OFF_WA     = OFF_ADJA   + (long long)N_ * N_;        // 18874369

// Scratch (device globals -- no allocation allowed)
__device__ float g_h  [ROWS * H_];   // h = x @ W^T            (8 MB)
__device__ float g_hp [ROWS * H_];   // elu(attn @ h)          (8 MB)
__device__ float g_xpw[ROWS * O_];   // x_proj + Wa            (4 MB)
__device__ float g_es [ROWS];
__device__ float g_ed [ROWS];
__device__ float g_mx [ROWS];
__device__ float g_rs [ROWS];

// ---------------------------------------------------------------------------
// K0: elementwise outputs: adj_A1 = clip(sinh(3*clip(adjA,-3,3)),+-1000),
//     eye, copies of adj_A / z_positive / Wa / z.
// NOTE: OFF_ZPOS / OFF_ADJA are odd float offsets -> scalar stores there.
// ---------------------------------------------------------------------------
__global__ void k0_misc(const float* __restrict__ adjA,
                        const float* __restrict__ zpos,
                        const float* __restrict__ Wa,
                        const float* __restrict__ z,
                        float* __restrict__ out)
{
    int i4 = blockIdx.x * blockDim.x + threadIdx.x;   // float4 index
    if (i4 < (N_ * N_ / 4)) {
        float4 a4  = ((const float4*)adjA)[i4];
        float4 zp4 = ((const float4*)zpos)[i4];
        int g = i4 * 4;

        // misaligned regions: scalar stores (4B alignment is safe)
        float* adja_dst = out + OFF_ADJA + g;
        float* zpos_dst = out + OFF_ZPOS + g;
        const float* ap = (const float*)&a4;
        const float* zp = (const float*)&zp4;
#pragma unroll
        for (int l = 0; l < 4; l++) { adja_dst[l] = ap[l]; zpos_dst[l] = zp[l]; }

        float4 s4; float* sp = (float*)&s4;
#pragma unroll
        for (int l = 0; l < 4; l++) {
            float c = fminf(fmaxf(ap[l], -3.f), 3.f);
            float s = sinhf(3.f * c);
            sp[l] = fminf(fmaxf(s, -1000.f), 1000.f);
        }
        ((float4*)(out + OFF_ADJ1))[i4] = s4;

        int row = g >> 11;
        int col = g & 2047;
        float4 e4; float* ep = (float*)&e4;
#pragma unroll
        for (int l = 0; l < 4; l++) ep[l] = (col + l == row) ? 1.f : 0.f;
        ((float4*)(out + OFF_EYE))[i4] = e4;
    }
    if (blockIdx.x == 0) {
        if (threadIdx.x < O_)  out[OFF_WA + threadIdx.x] = Wa[threadIdx.x];
        if (threadIdx.x == O_) out[OFF_Z] = z[0];
    }
}

// ---------------------------------------------------------------------------
// K1: h = x @ W^T   (rows = B*N, tile 64 rows x 128 cols, K=128 in chunks 32)
// ---------------------------------------------------------------------------
__global__ __launch_bounds__(256) void k1_h(const float* __restrict__ x,
                                            const float* __restrict__ W)
{
    __shared__ float x_s[64][33];
    __shared__ float w_s[32][129];
    const int m0 = blockIdx.x * 64;
    const int tid = threadIdx.x, tx = tid & 15, ty = tid >> 4;

    float acc[4][8];
#pragma unroll
    for (int i = 0; i < 4; i++)
#pragma unroll
        for (int j = 0; j < 8; j++) acc[i][j] = 0.f;

    for (int f0 = 0; f0 < F_; f0 += 32) {
#pragma unroll
        for (int it = 0; it < 8; it++) {           // 64x32 x tile
            int idx = tid + it * 256;
            int mi = idx >> 5, k = idx & 31;
            x_s[mi][k] = x[(m0 + mi) * F_ + f0 + k];
        }
#pragma unroll
        for (int it = 0; it < 16; it++) {          // 128x32 W chunk, transposed
            int idx = tid + it * 256;
            int h = idx >> 5, k = idx & 31;
            w_s[k][h] = W[h * F_ + f0 + k];
        }
        __syncthreads();
#pragma unroll
        for (int k = 0; k < 32; k++) {
            float a[4], b[8];
#pragma unroll
            for (int i = 0; i < 4; i++) a[i] = x_s[ty + 16 * i][k];
#pragma unroll
            for (int j = 0; j < 8; j++) b[j] = w_s[k][tx + 16 * j];
#pragma unroll
            for (int i = 0; i < 4; i++)
#pragma unroll
                for (int j = 0; j < 8; j++) acc[i][j] += a[i] * b[j];
        }
        __syncthreads();
    }
#pragma unroll
    for (int i = 0; i < 4; i++) {
        int r = m0 + ty + 16 * i;
#pragma unroll
        for (int j = 0; j < 8; j++)
            g_h[r * H_ + tx + 16 * j] = acc[i][j];
    }
}

// ---------------------------------------------------------------------------
// K1b: e_src / e_dst (one warp per row)
// ---------------------------------------------------------------------------
__global__ void k1b_e(const float* __restrict__ a_src,
                      const float* __restrict__ a_dst)
{
    int warp = threadIdx.x >> 5, lane = threadIdx.x & 31;
    int r = blockIdx.x * 8 + warp;
    float s1 = 0.f, s2 = 0.f;
#pragma unroll
    for (int t = 0; t < 4; t++) {
        int h = lane + 32 * t;
        float v = g_h[r * H_ + h];
        s1 += v * a_src[h];
        s2 += v * a_dst[h];
    }
#pragma unroll
    for (int off = 16; off >= 1; off >>= 1) {
        s1 += __shfl_xor_sync(0xffffffffu, s1, off);
        s2 += __shfl_xor_sync(0xffffffffu, s2, off);
    }
    if (lane == 0) { g_es[r] = s1; g_ed[r] = s2; }
}

// ---------------------------------------------------------------------------
// K2: softmax row stats (max, 1/sum) -- one warp per (b,m) row.
// score(n) = masked ? NEG_INF : lrelu(es+ed_n); masked iff adjA[m,n]+I <= 0.
// ---------------------------------------------------------------------------
__global__ void k2_stats(const float* __restrict__ adjA)
{
    int warp = threadIdx.x >> 5, lane = threadIdx.x & 31;
    int r = blockIdx.x * 8 + warp;
    int m = r & 2047;
    const float* edb  = g_ed + (r & ~2047);
    const float* arow = adjA + (long long)m * N_;
    const float es = g_es[r];

    float mx = -INFINITY;
    for (int n = lane; n < N_; n += 32) {
        float adj = arow[n] + (n == m ? 1.f : 0.f);
        float v = es + edb[n];
        float lr = v >= 0.f ? v : 0.2f * v;
        float sc = (adj <= 0.f) ? NEG_INF : lr;
        mx = fmaxf(mx, sc);
    }
#pragma unroll
    for (int off = 16; off >= 1; off >>= 1)
        mx = fmaxf(mx, __shfl_xor_sync(0xffffffffu, mx, off));

    float sm = 0.f;
    for (int n = lane; n < N_; n += 32) {
        float adj = arow[n] + (n == m ? 1.f : 0.f);
        float v = es + edb[n];
        float lr = v >= 0.f ? v : 0.2f * v;
        float sc = (adj <= 0.f) ? NEG_INF : lr;
        sm += __expf(sc - mx);
    }
#pragma unroll
    for (int off = 16; off >= 1; off >>= 1)
        sm += __shfl_xor_sync(0xffffffffu, sm, off);

    if (lane == 0) { g_mx[r] = mx; g_rs[r] = 1.f / sm; }
}

// ---------------------------------------------------------------------------
// K3: h_prime = elu(attn @ h).  One block per (b, 64-row m-tile).
// attn weights computed on the fly (never materialized).
// ---------------------------------------------------------------------------
__global__ __launch_bounds__(256) void k3_attn(const float* __restrict__ adjA)
{
    __shared__ float h_s[32][128];
    __shared__ float w_s[64][33];
    __shared__ float s_mx[64], s_rs[64], s_es[64];

    const int b  = blockIdx.x >> 5;
    const int m0 = (blockIdx.x & 31) * 64;
    const int rbase = b * N_ + m0;
    const int tid = threadIdx.x, tx = tid & 15, ty = tid >> 4;

    if (tid < 64) {
        s_mx[tid] = g_mx[rbase + tid];
        s_rs[tid] = g_rs[rbase + tid];
        s_es[tid] = g_es[rbase + tid];
    }
    __syncthreads();

    float acc[4][8];
#pragma unroll
    for (int i = 0; i < 4; i++)
#pragma unroll
        for (int j = 0; j < 8; j++) acc[i][j] = 0.f;

    const int mi = tid >> 2;            // 0..63  (w-row this thread fills)
    const int nb = (tid & 3) * 8;       // 8 n's per thread
    const int gm = m0 + mi;
    const float* arow = adjA + (long long)gm * N_;
    const float* edb  = g_ed + b * N_;
    const float es = s_es[mi], mx = s_mx[mi], rs = s_rs[mi];

    for (int n0 = 0; n0 < N_; n0 += 32) {
        // load h tile [32 n x 128 h]
#pragma unroll
        for (int it = 0; it < 16; it++) {
            int idx = tid + it * 256;
            int k = idx >> 7, c = idx & 127;
            h_s[k][c] = g_h[(b * N_ + n0 + k) * H_ + c];
        }
        // compute softmax weights for this 64x32 tile
        float4 a4[2], e4[2];
        a4[0] = *(const float4*)(arow + n0 + nb);
        a4[1] = *(const float4*)(arow + n0 + nb + 4);
        e4[0] = *(const float4*)(edb  + n0 + nb);
        e4[1] = *(const float4*)(edb  + n0 + nb + 4);
        const float* ap = (const float*)a4;
        const float* ep = (const float*)e4;
#pragma unroll
        for (int jj = 0; jj < 8; jj++) {
            int n = n0 + nb + jj;
            float adj = ap[jj] + (n == gm ? 1.f : 0.f);
            float v = es + ep[jj];
            float lr = v >= 0.f ? v : 0.2f * v;
            float sc = (adj <= 0.f) ? NEG_INF : lr;
            w_s[mi][nb + jj] = __expf(sc - mx) * rs;
        }
        __syncthreads();
#pragma unroll
        for (int k = 0; k < 32; k++) {
            float a[4], bb[8];
#pragma unroll
            for (int i = 0; i < 4; i++) a[i] = w_s[ty + 16 * i][k];
#pragma unroll
            for (int j = 0; j < 8; j++) bb[j] = h_s[k][tx + 16 * j];
#pragma unroll
            for (int i = 0; i < 4; i++)
#pragma unroll
                for (int j = 0; j < 8; j++) acc[i][j] += a[i] * bb[j];
        }
        __syncthreads();
    }
    // elu epilogue -> g_hp
#pragma unroll
    for (int i = 0; i < 4; i++) {
        int r = rbase + ty + 16 * i;
#pragma unroll
        for (int j = 0; j < 8; j++) {
            float v = acc[i][j];
            float e = v > 0.f ? v : expm1f(v);
            g_hp[r * H_ + tx + 16 * j] = e;
        }
    }
}

// ---------------------------------------------------------------------------
// K4: x_proj = hp @ fc2_w^T + fc2_b ; also stash xpw = x_proj + Wa
// ---------------------------------------------------------------------------
__global__ __launch_bounds__(256) void k4_xproj(const float* __restrict__ fc2w,
                                                const float* __restrict__ fc2b,
                                                const float* __restrict__ Wa,
                                                float* __restrict__ out)
{
    __shared__ float a_s[64][33];
    __shared__ float b_s[32][65];
    const int m0 = blockIdx.x * 64;
    const int tid = threadIdx.x, tx = tid & 15, ty = tid >> 4;

    float acc[4][4];
#pragma unroll
    for (int i = 0; i < 4; i++)
#pragma unroll
        for (int j = 0; j < 4; j++) acc[i][j] = 0.f;

    for (int f0 = 0; f0 < H_; f0 += 32) {
#pragma unroll
        for (int it = 0; it < 8; it++) {
            int idx = tid + it * 256;
            int mi = idx >> 5, k = idx & 31;
            a_s[mi][k] = g_hp[(m0 + mi) * H_ + f0 + k];
        }
#pragma unroll
        for (int it = 0; it < 8; it++) {
            int idx = tid + it * 256;
            int o = idx >> 5, k = idx & 31;
            b_s[k][o] = fc2w[o * H_ + f0 + k];
        }
        __syncthreads();
#pragma unroll
        for (int k = 0; k < 32; k++) {
            float a[4], bb[4];
#pragma unroll
            for (int i = 0; i < 4; i++) a[i] = a_s[ty + 16 * i][k];
#pragma unroll
            for (int j = 0; j < 4; j++) bb[j] = b_s[k][tx + 16 * j];
#pragma unroll
            for (int i = 0; i < 4; i++)
#pragma unroll
                for (int j = 0; j < 4; j++) acc[i][j] += a[i] * bb[j];
        }
        __syncthreads();
    }
#pragma unroll
    for (int i = 0; i < 4; i++) {
        int r = m0 + ty + 16 * i;
#pragma unroll
        for (int j = 0; j < 4; j++) {
            int c = tx + 16 * j;
            float v = acc[i][j] + fc2b[c];
            out[OFF_XPROJ + (long long)r * O_ + c] = v;
            g_xpw[r * O_ + c] = v + Wa[c];
        }
    }
}

// ---------------------------------------------------------------------------
// K5: logits[b,m,o] = x_proj[b,m,o] - sum_n adj_A1[n,m] * xpw[b,n,o]
// ---------------------------------------------------------------------------
__global__ __launch_bounds__(256) void k5_logits(float* __restrict__ out)
{
    __shared__ float a_s[32][65];
    __shared__ float b_s[32][65];
    const int b  = blockIdx.x >> 5;
    const int m0 = (blockIdx.x & 31) * 64;
    const int tid = threadIdx.x, tx = tid & 15, ty = tid >> 4;
    const float* A1 = out + OFF_ADJ1;

    float acc[4][4];
#pragma unroll
    for (int i = 0; i < 4; i++)
#pragma unroll
        for (int j = 0; j < 4; j++) acc[i][j] = 0.f;

    for (int n0 = 0; n0 < N_; n0 += 32) {
#pragma unroll
        for (int it = 0; it < 8; it++) {       // A1^T tile: a_s[k][m] = A1[n0+k][m0+m]
            int idx = tid + it * 256;
            int k = idx >> 6, m = idx & 63;
            a_s[k][m] = A1[(long long)(n0 + k) * N_ + m0 + m];
        }
#pragma unroll
        for (int it = 0; it < 8; it++) {       // xpw tile
            int idx = tid + it * 256;
            int k = idx >> 6, o = idx & 63;
            b_s[k][o] = g_xpw[(b * N_ + n0 + k) * O_ + o];
        }
        __syncthreads();
#pragma unroll
        for (int k = 0; k < 32; k++) {
            float a[4], bb[4];
#pragma unroll
            for (int i = 0; i < 4; i++) a[i] = a_s[k][ty + 16 * i];
#pragma unroll
            for (int j = 0; j < 4; j++) bb[j] = b_s[k][tx + 16 * j];
#pragma unroll
            for (int i = 0; i < 4; i++)
#pragma unroll
                for (int j = 0; j < 4; j++) acc[i][j] += a[i] * bb[j];
        }
        __syncthreads();
    }
#pragma unroll
    for (int i = 0; i < 4; i++) {
        int r = b * N_ + m0 + ty + 16 * i;
#pragma unroll
        for (int j = 0; j < 4; j++) {
            int c = tx + 16 * j;
            out[OFF_LOGITS + (long long)r * O_ + c] =
                out[OFF_XPROJ + (long long)r * O_ + c] - acc[i][j];
        }
    }
}

// ---------------------------------------------------------------------------
extern "C" void kernel_launch(void* const* d_in, const int* in_sizes, int n_in,
                              void* d_out, int out_size)
{
    const float* x     = (const float*)d_in[0];
    const float* adjA  = (const float*)d_in[1];
    const float* W     = (const float*)d_in[2];
    const float* a_src = (const float*)d_in[3];
    const float* a_dst = (const float*)d_in[4];
    const float* fc2w  = (const float*)d_in[5];
    const float* fc2b  = (const float*)d_in[6];
    const float* Wa    = (const float*)d_in[7];
    const float* z     = (const float*)d_in[8];
    const float* zpos  = (const float*)d_in[9];
    float* out = (float*)d_out;

    k0_misc  <<<(N_ * N_ / 4 + 255) / 256, 256>>>(adjA, zpos, Wa, z, out);
    k1_h     <<<ROWS / 64, 256>>>(x, W);
    k1b_e    <<<ROWS / 8, 256>>>(a_src, a_dst);
    k2_stats <<<ROWS / 8, 256>>>(adjA);
    k3_attn  <<<B_ * (N_ / 64), 256>>>(adjA);
    k4_xproj <<<ROWS / 64, 256>>>(fc2w, fc2b, Wa, out);
    k5_logits<<<B_ * (N_ / 64), 256>>>(out);
}